// round 3
// baseline (speedup 1.0000x reference)
#include <cuda_runtime.h>

// Problem constants
#define BB 16
#define SS 64
#define TT_ 4096
#define CC 512
#define HH 8
#define DD 64

// Scratch (device globals: allocation-free rule)
__device__ float g_q[CC];                           // Wq@x + bq
__device__ float g_w[HH * CC];                      // folded query-side weights
__device__ float g_cb[CC];                          // bp + Wp @ bv
__device__ float g_att[BB * HH * TT_];              // 2 MB logits
__device__ float g_m[(size_t)BB * SS * HH * CC];    // 16 MB softmax-weighted eh sums
__device__ float g_tmp[BB * SS * CC];               // 2 MB per-head V-projected

__device__ __forceinline__ float warp_red_max(float v) {
#pragma unroll
    for (int o = 16; o; o >>= 1) v = fmaxf(v, __shfl_xor_sync(0xffffffffu, v, o));
    return v;
}
__device__ __forceinline__ float warp_red_sum(float v) {
#pragma unroll
    for (int o = 16; o; o >>= 1) v += __shfl_xor_sync(0xffffffffu, v, o);
    return v;
}

// ---------------------------------------------------------------------------
// Setup stage 1: q = Wq@x + bq ; cb = bp + Wp@bv.
// grid 32 x 512 threads: warp per output row, each warp does one Wq row and
// one Wp row (coalesced along c).
// ---------------------------------------------------------------------------
__global__ void setup1_kernel(const float* __restrict__ x, const float* __restrict__ Wq,
                              const float* __restrict__ bq, const float* __restrict__ Wp,
                              const float* __restrict__ bv, const float* __restrict__ bp) {
    __shared__ float xs[CC], bvs[CC];
    int tid = threadIdx.x, lane = tid & 31, wid = tid >> 5;  // 16 warps
    xs[tid] = x[tid];
    bvs[tid] = bv[tid];
    __syncthreads();

    int o = blockIdx.x * 16 + wid;  // 0..511
    {
        const float* r = Wq + (size_t)o * CC;
        float s = 0.f;
#pragma unroll 4
        for (int c = lane; c < CC; c += 32) s += r[c] * xs[c];
        s = warp_red_sum(s);
        if (lane == 0) g_q[o] = s + bq[o];
    }
    {
        const float* r = Wp + (size_t)o * CC;
        float s = 0.f;
#pragma unroll 4
        for (int c = lane; c < CC; c += 32) s += r[c] * bvs[c];
        s = warp_red_sum(s);
        if (lane == 0) g_cb[o] = s + bp[o];
    }
}

// ---------------------------------------------------------------------------
// Setup stage 2: w[h,c] = (1/8) * sum_d q[h*64+d] * Wk[h*64+d, c]
// grid 8 (one per head) x 512 threads; Wk rows read coalesced.
// ---------------------------------------------------------------------------
__global__ void setup2_kernel(const float* __restrict__ Wk) {
    __shared__ float qh[DD];
    int h = blockIdx.x, tid = threadIdx.x;
    if (tid < DD) qh[tid] = g_q[h * DD + tid];
    __syncthreads();
    const float* base = Wk + (size_t)h * DD * CC + tid;
    float s = 0.f;
#pragma unroll 8
    for (int d = 0; d < DD; d++) s = fmaf(qh[d], base[(size_t)d * CC], s);
    g_w[h * CC + tid] = 0.125f * s;  // 1/sqrt(64)
}

// ---------------------------------------------------------------------------
// att[b,h,t] = w[h,:] . eh[b,:,t]   (memory bound: one full eh read)
// grid (T/256, B), 256 threads, thread owns one t.
// ---------------------------------------------------------------------------
__global__ void att_kernel(const float* __restrict__ eh) {
    __shared__ float ws[HH * CC];
    int tid = threadIdx.x;
    for (int i = tid; i < HH * CC; i += 256) ws[i] = g_w[i];
    __syncthreads();

    int b = blockIdx.y;
    int t = blockIdx.x * 256 + tid;
    const float* e = eh + (size_t)b * CC * TT_ + t;
    float acc[HH];
#pragma unroll
    for (int h = 0; h < HH; h++) acc[h] = 0.f;

#pragma unroll 8
    for (int c = 0; c < CC; c++) {
        float v = e[(size_t)c * TT_];
#pragma unroll
        for (int h = 0; h < HH; h++) acc[h] = fmaf(ws[h * CC + c], v, acc[h]);
    }
    float* ao = g_att + (size_t)b * HH * TT_ + t;
#pragma unroll
    for (int h = 0; h < HH; h++) ao[(size_t)h * TT_] = acc[h];
}

// ---------------------------------------------------------------------------
// Per (b,s): softmax stats over segment, then m[h,c] = sum_t p[h,t]*eh[c,t].
// Second full eh read. 128 threads; thread owns 4 channels (tid + k*128) with
// register accumulators, so inner loop is 12 LDS per 32 FMA.
// grid (B*S), 128 threads.
// ---------------------------------------------------------------------------
#define SEG_TT 16
__global__ void seg_kernel(const float* __restrict__ eh, const int* __restrict__ ss,
                           const int* __restrict__ se) {
    __shared__ float tile[CC][SEG_TT + 1];  // 34.8 KB, conflict-free transpose
    __shared__ float ps[HH][SEG_TT];
    __shared__ float smax[HH], sinv[HH];
    __shared__ float wred[4][HH];

    int bid = blockIdx.x;
    int b = bid >> 6;
    int st = ss[bid], en = se[bid];  // en > st guaranteed
    int tid = threadIdx.x, lane = tid & 31, wid = tid >> 5;  // 4 warps
    const float* ebase = eh + (size_t)b * CC * TT_;
    const float* abase = g_att + (size_t)b * HH * TT_;

    // phase 1: per-head max over [st, en)
    float mx[HH];
#pragma unroll
    for (int h = 0; h < HH; h++) mx[h] = -3.0e38f;
    for (int t = st + tid; t < en; t += 128) {
#pragma unroll
        for (int h = 0; h < HH; h++) mx[h] = fmaxf(mx[h], abase[(size_t)h * TT_ + t]);
    }
#pragma unroll
    for (int h = 0; h < HH; h++) mx[h] = warp_red_max(mx[h]);
    if (lane == 0) {
        for (int h = 0; h < HH; h++) wred[wid][h] = mx[h];
    }
    __syncthreads();
    if (tid < HH) {
        float v = wred[0][tid];
        for (int w = 1; w < 4; w++) v = fmaxf(v, wred[w][tid]);
        smax[tid] = v;
    }
    __syncthreads();

    // phase 2: per-head sum of exp
    float sm[HH];
#pragma unroll
    for (int h = 0; h < HH; h++) sm[h] = 0.f;
    for (int t = st + tid; t < en; t += 128) {
#pragma unroll
        for (int h = 0; h < HH; h++) sm[h] += __expf(abase[(size_t)h * TT_ + t] - smax[h]);
    }
#pragma unroll
    for (int h = 0; h < HH; h++) sm[h] = warp_red_sum(sm[h]);
    if (lane == 0) {
        for (int h = 0; h < HH; h++) wred[wid][h] = sm[h];
    }
    __syncthreads();
    if (tid < HH) {
        float v = 0.f;
        for (int w = 0; w < 4; w++) v += wred[w][tid];
        sinv[tid] = 1.f / v;  // >= 1, safe
    }
    __syncthreads();

    // phase 3: weighted accumulation; thread owns c = tid + k*128, k=0..3
    float acc[4][HH];
#pragma unroll
    for (int k = 0; k < 4; k++)
#pragma unroll
        for (int h = 0; h < HH; h++) acc[k][h] = 0.f;

    for (int t0 = st & ~(SEG_TT - 1); t0 < en; t0 += SEG_TT) {
        __syncthreads();  // previous chunk's compute done before overwrite
        {
            int h = tid >> 4, j = tid & 15;  // 128 = 8h * 16j exactly
            int t = t0 + j;
            ps[h][j] = (t >= st && t < en)
                           ? __expf(abase[(size_t)h * TT_ + t] - smax[h]) * sinv[h]
                           : 0.f;
        }
#pragma unroll 8
        for (int i = 0; i < 64; i++) {
            int idx = tid + i * 128;
            int c = idx >> 4, j = idx & 15;
            int t = t0 + j;
            tile[c][j] = (t < en) ? ebase[(size_t)c * TT_ + t] : 0.f;
        }
        __syncthreads();
#pragma unroll 4
        for (int j = 0; j < SEG_TT; j++) {
            float p[HH];
#pragma unroll
            for (int h = 0; h < HH; h++) p[h] = ps[h][j];
            float e0 = tile[tid][j];
            float e1 = tile[tid + 128][j];
            float e2 = tile[tid + 256][j];
            float e3 = tile[tid + 384][j];
#pragma unroll
            for (int h = 0; h < HH; h++) {
                acc[0][h] = fmaf(p[h], e0, acc[0][h]);
                acc[1][h] = fmaf(p[h], e1, acc[1][h]);
                acc[2][h] = fmaf(p[h], e2, acc[2][h]);
                acc[3][h] = fmaf(p[h], e3, acc[3][h]);
            }
        }
    }

    float* mo = g_m + (size_t)bid * HH * CC;
#pragma unroll
    for (int h = 0; h < HH; h++) {
#pragma unroll
        for (int k = 0; k < 4; k++) mo[h * CC + tid + k * 128] = acc[k][h];
    }
}

// ---------------------------------------------------------------------------
// fp32 tiled GEMM: C[m,n] (+= bias[n]) = sum_k A[m,k] * B[n,k]
// 32x64 tile, K-chunk 32, 256 threads, 2x4 microtile, smem stored [k][mn].
// Small tile -> 256+ blocks -> occupancy (round-2 gemm was grid=128, occ 12%).
// ---------------------------------------------------------------------------
__device__ __forceinline__ void gemm_body(const float* __restrict__ A,
                                          const float* __restrict__ Bm,
                                          float* __restrict__ Cm,
                                          const float* __restrict__ bias,
                                          int lda, int ldb, int ldc, int K) {
    __shared__ float As[32][34];  // 136B rows: float2-aligned, 2-way store conflicts
    __shared__ float Bs[32][68];  // 272B rows: float4-aligned
    int tid = threadIdx.x;
    int tx = tid & 15, ty = tid >> 4;  // tx: n/4, ty: m/2
    int m0 = blockIdx.x * 32, n0 = blockIdx.y * 64;
    float acc[2][4];
#pragma unroll
    for (int i = 0; i < 2; i++)
#pragma unroll
        for (int j = 0; j < 4; j++) acc[i][j] = 0.f;

    for (int k0 = 0; k0 < K; k0 += 32) {
        // A: 32x32 = 1024 elems, 4 per thread
#pragma unroll
        for (int i = 0; i < 4; i++) {
            int idx = tid + i * 256;
            int row = idx >> 5, col = idx & 31;
            As[col][row] = A[(size_t)(m0 + row) * lda + k0 + col];
        }
        // B: 64x32 = 2048 elems, 8 per thread
#pragma unroll
        for (int i = 0; i < 8; i++) {
            int idx = tid + i * 256;
            int row = idx >> 5, col = idx & 31;
            Bs[col][row] = Bm[(size_t)(n0 + row) * ldb + k0 + col];
        }
        __syncthreads();
#pragma unroll
        for (int kk = 0; kk < 32; kk++) {
            float2 a2 = *(const float2*)&As[kk][ty * 2];
            float4 b4 = *(const float4*)&Bs[kk][tx * 4];
            float a[2] = {a2.x, a2.y};
            float bb[4] = {b4.x, b4.y, b4.z, b4.w};
#pragma unroll
            for (int i = 0; i < 2; i++)
#pragma unroll
                for (int j = 0; j < 4; j++) acc[i][j] = fmaf(a[i], bb[j], acc[i][j]);
        }
        __syncthreads();
    }
#pragma unroll
    for (int i = 0; i < 2; i++) {
        int mm = m0 + ty * 2 + i;
#pragma unroll
        for (int j = 0; j < 4; j++) {
            int nn = n0 + tx * 4 + j;
            float v = acc[i][j];
            if (bias) v += bias[nn];
            Cm[(size_t)mm * ldc + nn] = v;
        }
    }
}

// D1: tmp[r, h*64+d] = sum_c m[r,h,c] * Wv[h*64+d, c]   (grid 32 x 1 x 8)
__global__ void gemm1_kernel(const float* __restrict__ Wv) {
    int h = blockIdx.z;
    gemm_body(g_m + h * CC, Wv + (size_t)h * DD * CC, g_tmp + h * DD,
              nullptr, HH * CC, CC, CC, CC);
}

// D2: y[r,o] = sum_i tmp[r,i] * Wp[o,i] + cb[o]          (grid 32 x 8)
__global__ void gemm2_kernel(const float* __restrict__ Wp, float* __restrict__ out) {
    gemm_body(g_tmp, Wp, out, g_cb, CC, CC, CC, CC);
}

// ---------------------------------------------------------------------------
extern "C" void kernel_launch(void* const* d_in, const int* in_sizes, int n_in,
                              void* d_out, int out_size) {
    const float* x  = (const float*)d_in[0];
    const float* eh = (const float*)d_in[1];
    const int*   st = (const int*)d_in[2];
    const int*   en = (const int*)d_in[3];
    const float* Wq = (const float*)d_in[4];
    const float* bq = (const float*)d_in[5];
    const float* Wk = (const float*)d_in[6];
    /* d_in[7] = bk: per-head constant in logits, cancels in softmax */
    const float* Wv = (const float*)d_in[8];
    const float* bv = (const float*)d_in[9];
    const float* Wp = (const float*)d_in[10];
    const float* bp = (const float*)d_in[11];
    float* out = (float*)d_out;

    setup1_kernel<<<32, 512>>>(x, Wq, bq, Wp, bv, bp);
    setup2_kernel<<<HH, CC>>>(Wk);
    att_kernel<<<dim3(TT_ / 256, BB), 256>>>(eh);
    seg_kernel<<<BB * SS, 128>>>(eh, st, en);
    gemm1_kernel<<<dim3(BB * SS / 32, 1, HH), 256>>>(Wv);
    gemm2_kernel<<<dim3(BB * SS / 32, CC / 64, 1), 256>>>(Wp, out);
}

// round 4
// speedup vs baseline: 1.4106x; 1.4106x over previous
#include <cuda_runtime.h>
#include <cstdint>

// Problem constants
#define BB 16
#define SS 64
#define TT_ 4096
#define CC 512
#define HH 8
#define DD 64

#define TSTR 20      // tile row stride (floats): 80B rows -> cp.async 16B aligned,
                     // LDS.128 at 80B lane stride is bank-conflict-free (5c mod 8 distinct)
#define MEGA 256     // t-positions of probabilities staged per outer iteration
#define SEG_SMEM ((2 * CC * TSTR + MEGA * HH) * 4)   // 90112 B

// Scratch (device globals: allocation-free rule)
__device__ float g_q[CC];
__device__ float g_w[HH * CC];
__device__ float g_cb[CC];
__device__ float g_att[BB * HH * TT_];
__device__ float g_m[(size_t)BB * SS * HH * CC];
__device__ float g_tmp[BB * SS * CC];

__device__ __forceinline__ float warp_red_max(float v) {
#pragma unroll
    for (int o = 16; o; o >>= 1) v = fmaxf(v, __shfl_xor_sync(0xffffffffu, v, o));
    return v;
}
__device__ __forceinline__ float warp_red_sum(float v) {
#pragma unroll
    for (int o = 16; o; o >>= 1) v += __shfl_xor_sync(0xffffffffu, v, o);
    return v;
}

// ---------------------------------------------------------------------------
// Setup stage 1: q = Wq@x + bq ; cb = bp + Wp@bv. grid 32 x 512.
// ---------------------------------------------------------------------------
__global__ void setup1_kernel(const float* __restrict__ x, const float* __restrict__ Wq,
                              const float* __restrict__ bq, const float* __restrict__ Wp,
                              const float* __restrict__ bv, const float* __restrict__ bp) {
    __shared__ float xs[CC], bvs[CC];
    int tid = threadIdx.x, lane = tid & 31, wid = tid >> 5;
    xs[tid] = x[tid];
    bvs[tid] = bv[tid];
    __syncthreads();

    int o = blockIdx.x * 16 + wid;
    {
        const float* r = Wq + (size_t)o * CC;
        float s = 0.f;
#pragma unroll 4
        for (int c = lane; c < CC; c += 32) s += r[c] * xs[c];
        s = warp_red_sum(s);
        if (lane == 0) g_q[o] = s + bq[o];
    }
    {
        const float* r = Wp + (size_t)o * CC;
        float s = 0.f;
#pragma unroll 4
        for (int c = lane; c < CC; c += 32) s += r[c] * bvs[c];
        s = warp_red_sum(s);
        if (lane == 0) g_cb[o] = s + bp[o];
    }
}

// ---------------------------------------------------------------------------
// Setup stage 2: w[h,c] = (1/8) * sum_d q[h*64+d] * Wk[h*64+d, c].  grid 8 x 512.
// ---------------------------------------------------------------------------
__global__ void setup2_kernel(const float* __restrict__ Wk) {
    __shared__ float qh[DD];
    int h = blockIdx.x, tid = threadIdx.x;
    if (tid < DD) qh[tid] = g_q[h * DD + tid];
    __syncthreads();
    const float* base = Wk + (size_t)h * DD * CC + tid;
    float s = 0.f;
#pragma unroll 8
    for (int d = 0; d < DD; d++) s = fmaf(qh[d], base[(size_t)d * CC], s);
    g_w[h * CC + tid] = 0.125f * s;
}

// ---------------------------------------------------------------------------
// Init: g_tmp = 0 (split-K atomic target), out = broadcast bias cb.
// grid 2048 x 256. Runs after setup1 (needs g_cb).
// ---------------------------------------------------------------------------
__global__ void init_kernel(float* __restrict__ out) {
    int idx = blockIdx.x * 256 + threadIdx.x;
    g_tmp[idx] = 0.f;
    out[idx] = g_cb[idx & (CC - 1)];
}

// ---------------------------------------------------------------------------
// att[b,h,t] = w[h,:] . eh[b,:,t].  grid (16,16) x 256.
// ---------------------------------------------------------------------------
__global__ void att_kernel(const float* __restrict__ eh) {
    __shared__ float ws[HH * CC];
    int tid = threadIdx.x;
    for (int i = tid; i < HH * CC; i += 256) ws[i] = g_w[i];
    __syncthreads();

    int b = blockIdx.y;
    int t = blockIdx.x * 256 + tid;
    const float* e = eh + (size_t)b * CC * TT_ + t;
    float acc[HH];
#pragma unroll
    for (int h = 0; h < HH; h++) acc[h] = 0.f;

#pragma unroll 8
    for (int c = 0; c < CC; c++) {
        float v = e[(size_t)c * TT_];
#pragma unroll
        for (int h = 0; h < HH; h++) acc[h] = fmaf(ws[h * CC + c], v, acc[h]);
    }
    float* ao = g_att + (size_t)b * HH * TT_ + t;
#pragma unroll
    for (int h = 0; h < HH; h++) ao[(size_t)h * TT_] = acc[h];
}

// ---------------------------------------------------------------------------
// seg: per (b,s) softmax over segment then m[h,c] = sum_t p[h,t]*eh[c,t].
// 256 threads. cp.async double-buffered 512x16 eh tiles; per-mega (256 t)
// probabilities staged as ps[j][8] for broadcast LDS.128 reads.
// ---------------------------------------------------------------------------
__device__ __forceinline__ void seg_prefetch(float* dst, const float* __restrict__ ebase,
                                             int t0, int tid) {
#pragma unroll
    for (int k = 0; k < 8; k++) {
        int idx = tid + k * 256;          // 0..2047
        int row = idx >> 2;               // channel
        int s16 = (idx & 3) * 4;          // float offset of 16B piece
        const float* src = ebase + (size_t)row * TT_ + t0 + s16;
        uint32_t sa = (uint32_t)__cvta_generic_to_shared(dst + row * TSTR + s16);
        asm volatile("cp.async.cg.shared.global [%0], [%1], 16;\n" ::"r"(sa), "l"(src)
                     : "memory");
    }
}

extern __shared__ float dyn_smem[];

__global__ void seg_kernel(const float* __restrict__ eh, const int* __restrict__ ss,
                           const int* __restrict__ se) {
    float* tile0 = dyn_smem;                  // 512*20 floats
    float* tile1 = dyn_smem + CC * TSTR;      // 512*20 floats
    float* ps = dyn_smem + 2 * CC * TSTR;     // 256*8 floats, [j][h]
    __shared__ float smax[HH], sinv[HH];
    __shared__ float wred[8][HH];

    int bid = blockIdx.x;
    int b = bid >> 6;
    int st = ss[bid], en = se[bid];
    int tid = threadIdx.x, lane = tid & 31, wid = tid >> 5;
    const float* ebase = eh + (size_t)b * CC * TT_;
    const float* abase = g_att + (size_t)b * HH * TT_;

    // phase 1: per-head max
    float mx[HH];
#pragma unroll
    for (int h = 0; h < HH; h++) mx[h] = -3.0e38f;
    for (int t = st + tid; t < en; t += 256) {
#pragma unroll
        for (int h = 0; h < HH; h++) mx[h] = fmaxf(mx[h], abase[(size_t)h * TT_ + t]);
    }
#pragma unroll
    for (int h = 0; h < HH; h++) mx[h] = warp_red_max(mx[h]);
    if (lane == 0)
        for (int h = 0; h < HH; h++) wred[wid][h] = mx[h];
    __syncthreads();
    if (tid < HH) {
        float v = wred[0][tid];
        for (int w = 1; w < 8; w++) v = fmaxf(v, wred[w][tid]);
        smax[tid] = v;
    }
    __syncthreads();

    // phase 2: per-head sum of exp
    float sm[HH];
#pragma unroll
    for (int h = 0; h < HH; h++) sm[h] = 0.f;
    for (int t = st + tid; t < en; t += 256) {
#pragma unroll
        for (int h = 0; h < HH; h++) sm[h] += __expf(abase[(size_t)h * TT_ + t] - smax[h]);
    }
#pragma unroll
    for (int h = 0; h < HH; h++) sm[h] = warp_red_sum(sm[h]);
    if (lane == 0)
        for (int h = 0; h < HH; h++) wred[wid][h] = sm[h];
    __syncthreads();
    if (tid < HH) {
        float v = 0.f;
        for (int w = 0; w < 8; w++) v += wred[w][tid];
        sinv[tid] = 1.f / v;
    }
    __syncthreads();

    // phase 3: thread owns channels c0=tid, c1=tid+256
    float acc0[HH], acc1[HH];
#pragma unroll
    for (int h = 0; h < HH; h++) { acc0[h] = 0.f; acc1[h] = 0.f; }

    int t_lo = st & ~15;
    for (int mega = t_lo; mega < en; mega += MEGA) {
        // stage probabilities for this mega-chunk: ps[j*8+h]
#pragma unroll
        for (int k = 0; k < 8; k++) {
            int idx = tid + k * 256;
            int j = idx >> 3, h = idx & 7;
            int t = mega + j;
            float v = 0.f;
            if (t >= st && t < en)
                v = __expf(abase[(size_t)h * TT_ + t] - smax[h]) * sinv[h];
            ps[idx] = v;
        }
        __syncthreads();

        int mend = min(mega + MEGA, en);
        int nch = (mend - mega + 15) >> 4;

        seg_prefetch(tile0, ebase, mega, tid);
        asm volatile("cp.async.commit_group;\n" ::: "memory");

        for (int ci = 0; ci < nch; ci++) {
            float* tb = (ci & 1) ? tile1 : tile0;
            float* tn = (ci & 1) ? tile0 : tile1;
            bool more = (ci + 1 < nch);
            if (more) {
                seg_prefetch(tn, ebase, mega + (ci + 1) * 16, tid);
                asm volatile("cp.async.commit_group;\n" ::: "memory");
                asm volatile("cp.async.wait_group 1;\n" ::: "memory");
            } else {
                asm volatile("cp.async.wait_group 0;\n" ::: "memory");
            }
            __syncthreads();

            const float* pj = ps + ci * 16 * 8;
            const float* r0 = tb + tid * TSTR;
            const float* r1 = tb + (tid + 256) * TSTR;
#pragma unroll
            for (int jg = 0; jg < 4; jg++) {
                float4 e0 = *(const float4*)(r0 + jg * 4);
                float4 e1 = *(const float4*)(r1 + jg * 4);
                float ea[4] = {e0.x, e0.y, e0.z, e0.w};
                float eb[4] = {e1.x, e1.y, e1.z, e1.w};
#pragma unroll
                for (int jj = 0; jj < 4; jj++) {
                    float4 pA = *(const float4*)(pj + (jg * 4 + jj) * 8);
                    float4 pB = *(const float4*)(pj + (jg * 4 + jj) * 8 + 4);
                    float p[8] = {pA.x, pA.y, pA.z, pA.w, pB.x, pB.y, pB.z, pB.w};
#pragma unroll
                    for (int h = 0; h < HH; h++) {
                        acc0[h] = fmaf(p[h], ea[jj], acc0[h]);
                        acc1[h] = fmaf(p[h], eb[jj], acc1[h]);
                    }
                }
            }
            __syncthreads();  // compute done before this buffer is refilled
        }
    }

    float* mo = g_m + (size_t)bid * HH * CC;
#pragma unroll
    for (int h = 0; h < HH; h++) {
        mo[h * CC + tid] = acc0[h];
        mo[h * CC + tid + 256] = acc1[h];
    }
}

// ---------------------------------------------------------------------------
// fp32 tiled GEMM, 64x64 tile, split-K via [kbeg,kend), atomicAdd epilogue.
// C[m,n] += sum_k A[m,k]*B[n,k]. 256 threads, 4x4 micro.
// ---------------------------------------------------------------------------
__device__ __forceinline__ void gemm_body(const float* __restrict__ A,
                                          const float* __restrict__ Bm,
                                          float* __restrict__ Cm,
                                          int lda, int ldb, int ldc, int kbeg, int kend) {
    __shared__ float As[32][68];
    __shared__ float Bs[32][68];
    int tid = threadIdx.x;
    int tx = tid & 15, ty = tid >> 4;
    int m0 = blockIdx.x * 64, n0 = blockIdx.y * 64;
    float acc[4][4];
#pragma unroll
    for (int i = 0; i < 4; i++)
#pragma unroll
        for (int j = 0; j < 4; j++) acc[i][j] = 0.f;

    for (int k0 = kbeg; k0 < kend; k0 += 32) {
#pragma unroll
        for (int i = 0; i < 8; i++) {
            int idx = tid + i * 256;
            int row = idx >> 5, col = idx & 31;
            As[col][row] = A[(size_t)(m0 + row) * lda + k0 + col];
            Bs[col][row] = Bm[(size_t)(n0 + row) * ldb + k0 + col];
        }
        __syncthreads();
#pragma unroll
        for (int kk = 0; kk < 32; kk++) {
            float4 a4 = *(const float4*)&As[kk][ty * 4];
            float4 b4 = *(const float4*)&Bs[kk][tx * 4];
            float a[4] = {a4.x, a4.y, a4.z, a4.w};
            float bb[4] = {b4.x, b4.y, b4.z, b4.w};
#pragma unroll
            for (int i = 0; i < 4; i++)
#pragma unroll
                for (int j = 0; j < 4; j++) acc[i][j] = fmaf(a[i], bb[j], acc[i][j]);
        }
        __syncthreads();
    }
#pragma unroll
    for (int i = 0; i < 4; i++) {
        int mm = m0 + ty * 4 + i;
#pragma unroll
        for (int j = 0; j < 4; j++) {
            int nn = n0 + tx * 4 + j;
            atomicAdd(&Cm[(size_t)mm * ldc + nn], acc[i][j]);
        }
    }
}

// D1: tmp[r, h*64+d] += sum_c m[r,h,c]*Wv[h*64+d,c].  grid (16, 1, 16): z = h*2 + ksplit
__global__ void gemm1_kernel(const float* __restrict__ Wv) {
    int h = blockIdx.z >> 1;
    int kb = (blockIdx.z & 1) * 256;
    gemm_body(g_m + h * CC, Wv + (size_t)h * DD * CC, g_tmp + h * DD,
              HH * CC, CC, CC, kb, kb + 256);
}

// D2: out[r,o] += sum_i tmp[r,i]*Wp[o,i].  grid (16, 8, 2)
__global__ void gemm2_kernel(const float* __restrict__ Wp, float* __restrict__ out) {
    int kb = blockIdx.z * 256;
    gemm_body(g_tmp, Wp, out, CC, CC, CC, kb, kb + 256);
}

// ---------------------------------------------------------------------------
extern "C" void kernel_launch(void* const* d_in, const int* in_sizes, int n_in,
                              void* d_out, int out_size) {
    const float* x  = (const float*)d_in[0];
    const float* eh = (const float*)d_in[1];
    const int*   st = (const int*)d_in[2];
    const int*   en = (const int*)d_in[3];
    const float* Wq = (const float*)d_in[4];
    const float* bq = (const float*)d_in[5];
    const float* Wk = (const float*)d_in[6];
    /* d_in[7] = bk: constant per head in logits, cancels in softmax */
    const float* Wv = (const float*)d_in[8];
    const float* bv = (const float*)d_in[9];
    const float* Wp = (const float*)d_in[10];
    const float* bp = (const float*)d_in[11];
    float* out = (float*)d_out;

    static int smem_set = 0;
    if (!smem_set) {
        cudaFuncSetAttribute(seg_kernel, cudaFuncAttributeMaxDynamicSharedMemorySize,
                             SEG_SMEM);
        smem_set = 1;
    }

    setup1_kernel<<<32, 512>>>(x, Wq, bq, Wp, bv, bp);
    setup2_kernel<<<HH, CC>>>(Wk);
    init_kernel<<<2048, 256>>>(out);
    att_kernel<<<dim3(TT_ / 256, BB), 256>>>(eh);
    seg_kernel<<<BB * SS, 256, SEG_SMEM>>>(eh, st, en);
    gemm1_kernel<<<dim3(16, 1, 16), 256>>>(Wv);
    gemm2_kernel<<<dim3(16, 8, 2), 256>>>(Wp, out);
}

// round 5
// speedup vs baseline: 2.6305x; 1.8649x over previous
#include <cuda_runtime.h>
#include <cstdint>

// Problem constants
#define BB 16
#define SS 64
#define TT_ 4096
#define CC 512
#define HH 8
#define DD 64

#define TSTR 20      // seg tile row stride (floats): 80B rows, cp.async 16B aligned,
                     // LDS.128 at 80B lane stride is bank-conflict-free
#define MEGA 256     // t-positions of probabilities staged per outer iteration
#define SEG_SMEM ((2 * CC * TSTR + MEGA * HH) * 4)   // 90112 B

#define CSPLIT 4     // att channel split
#define CCH (CC / CSPLIT)   // 128 channels per att block

// Scratch (device globals: allocation-free rule)
__device__ float g_q[CC];
__device__ float g_w[HH * CC];
__device__ float g_cb[CC];
__device__ float g_att[BB * HH * TT_];
__device__ float g_m[(size_t)BB * SS * HH * CC];
__device__ float g_tmp[BB * SS * CC];

__device__ __forceinline__ float warp_red_max(float v) {
#pragma unroll
    for (int o = 16; o; o >>= 1) v = fmaxf(v, __shfl_xor_sync(0xffffffffu, v, o));
    return v;
}
__device__ __forceinline__ float warp_red_sum(float v) {
#pragma unroll
    for (int o = 16; o; o >>= 1) v += __shfl_xor_sync(0xffffffffu, v, o);
    return v;
}

// ---------------------------------------------------------------------------
// Setup stage 1: q = Wq@x + bq ; cb = bp + Wp@bv. grid 32 x 512.
// ---------------------------------------------------------------------------
__global__ void setup1_kernel(const float* __restrict__ x, const float* __restrict__ Wq,
                              const float* __restrict__ bq, const float* __restrict__ Wp,
                              const float* __restrict__ bv, const float* __restrict__ bp) {
    __shared__ float xs[CC], bvs[CC];
    int tid = threadIdx.x, lane = tid & 31, wid = tid >> 5;
    xs[tid] = x[tid];
    bvs[tid] = bv[tid];
    __syncthreads();

    int o = blockIdx.x * 16 + wid;
    {
        const float* r = Wq + (size_t)o * CC;
        float s = 0.f;
#pragma unroll 4
        for (int c = lane; c < CC; c += 32) s += r[c] * xs[c];
        s = warp_red_sum(s);
        if (lane == 0) g_q[o] = s + bq[o];
    }
    {
        const float* r = Wp + (size_t)o * CC;
        float s = 0.f;
#pragma unroll 4
        for (int c = lane; c < CC; c += 32) s += r[c] * bvs[c];
        s = warp_red_sum(s);
        if (lane == 0) g_cb[o] = s + bp[o];
    }
}

// ---------------------------------------------------------------------------
// Setup stage 2: w[h,c] = (1/8) * sum_d q[h*64+d] * Wk[h*64+d, c].  grid 8 x 512.
// ---------------------------------------------------------------------------
__global__ void setup2_kernel(const float* __restrict__ Wk) {
    __shared__ float qh[DD];
    int h = blockIdx.x, tid = threadIdx.x;
    if (tid < DD) qh[tid] = g_q[h * DD + tid];
    __syncthreads();
    const float* base = Wk + (size_t)h * DD * CC + tid;
    float s = 0.f;
#pragma unroll 8
    for (int d = 0; d < DD; d++) s = fmaf(qh[d], base[(size_t)d * CC], s);
    g_w[h * CC + tid] = 0.125f * s;
}

// ---------------------------------------------------------------------------
// Init: zero g_att (att atomic target) + g_tmp (split-K target), out = bias.
// grid 2048 x 256 -> 512K threads; g_att is 2M elems -> 4 per thread.
// Runs after setup1 (needs g_cb).
// ---------------------------------------------------------------------------
__global__ void init_kernel(float* __restrict__ out) {
    int idx = blockIdx.x * 256 + threadIdx.x;
    g_tmp[idx] = 0.f;
    out[idx] = g_cb[idx & (CC - 1)];
    float4* a4 = (float4*)g_att;
    a4[idx] = make_float4(0.f, 0.f, 0.f, 0.f);
}

// ---------------------------------------------------------------------------
// att v2: att[b,h,t] += w[h, cs:cs+128] . eh[b, cs:cs+128, t]
// grid (T/256, B, CSPLIT) = 1024 blocks x 256 threads. Weights staged
// transposed ws[c][h] -> inner loop: 1 LDG + 2 broadcast LDS.128 + 8 FFMA.
// Partials combined via atomicAdd (g_att zeroed by init_kernel).
// ---------------------------------------------------------------------------
__global__ void att_kernel(const float* __restrict__ eh) {
    __shared__ float ws[CCH][HH];  // [c][h], 4 KB
    int tid = threadIdx.x;
    int b = blockIdx.y;
    int cs = blockIdx.z * CCH;
    for (int idx = tid; idx < CCH * HH; idx += 256) {
        int c = idx >> 3, h = idx & 7;
        ws[c][h] = g_w[h * CC + cs + c];
    }
    __syncthreads();

    int t = blockIdx.x * 256 + tid;
    const float* e = eh + (size_t)b * CC * TT_ + (size_t)cs * TT_ + t;
    float acc[HH];
#pragma unroll
    for (int h = 0; h < HH; h++) acc[h] = 0.f;

#pragma unroll 8
    for (int c = 0; c < CCH; c++) {
        float v = e[(size_t)c * TT_];
        float4 w0 = *(const float4*)&ws[c][0];
        float4 w1 = *(const float4*)&ws[c][4];
        acc[0] = fmaf(w0.x, v, acc[0]);
        acc[1] = fmaf(w0.y, v, acc[1]);
        acc[2] = fmaf(w0.z, v, acc[2]);
        acc[3] = fmaf(w0.w, v, acc[3]);
        acc[4] = fmaf(w1.x, v, acc[4]);
        acc[5] = fmaf(w1.y, v, acc[5]);
        acc[6] = fmaf(w1.z, v, acc[6]);
        acc[7] = fmaf(w1.w, v, acc[7]);
    }
    float* ao = g_att + (size_t)b * HH * TT_ + t;
#pragma unroll
    for (int h = 0; h < HH; h++) atomicAdd(&ao[(size_t)h * TT_], acc[h]);
}

// ---------------------------------------------------------------------------
// seg: per (b,s) softmax over segment then m[h,c] = sum_t p[h,t]*eh[c,t].
// 256 threads. cp.async double-buffered 512x16 eh tiles; per-mega (256 t)
// probabilities staged as ps[j][8] for broadcast LDS.128 reads.
// ---------------------------------------------------------------------------
__device__ __forceinline__ void seg_prefetch(float* dst, const float* __restrict__ ebase,
                                             int t0, int tid) {
#pragma unroll
    for (int k = 0; k < 8; k++) {
        int idx = tid + k * 256;          // 0..2047
        int row = idx >> 2;               // channel
        int s16 = (idx & 3) * 4;          // float offset of 16B piece
        const float* src = ebase + (size_t)row * TT_ + t0 + s16;
        uint32_t sa = (uint32_t)__cvta_generic_to_shared(dst + row * TSTR + s16);
        asm volatile("cp.async.cg.shared.global [%0], [%1], 16;\n" ::"r"(sa), "l"(src)
                     : "memory");
    }
}

extern __shared__ float dyn_smem[];

__global__ void seg_kernel(const float* __restrict__ eh, const int* __restrict__ ss,
                           const int* __restrict__ se) {
    float* tile0 = dyn_smem;                  // 512*20 floats
    float* tile1 = dyn_smem + CC * TSTR;      // 512*20 floats
    float* ps = dyn_smem + 2 * CC * TSTR;     // 256*8 floats, [j][h]
    __shared__ float smax[HH], sinv[HH];
    __shared__ float wred[8][HH];

    int bid = blockIdx.x;
    int b = bid >> 6;
    int st = ss[bid], en = se[bid];
    int tid = threadIdx.x, lane = tid & 31, wid = tid >> 5;
    const float* ebase = eh + (size_t)b * CC * TT_;
    const float* abase = g_att + (size_t)b * HH * TT_;

    // phase 1: per-head max
    float mx[HH];
#pragma unroll
    for (int h = 0; h < HH; h++) mx[h] = -3.0e38f;
    for (int t = st + tid; t < en; t += 256) {
#pragma unroll
        for (int h = 0; h < HH; h++) mx[h] = fmaxf(mx[h], abase[(size_t)h * TT_ + t]);
    }
#pragma unroll
    for (int h = 0; h < HH; h++) mx[h] = warp_red_max(mx[h]);
    if (lane == 0)
        for (int h = 0; h < HH; h++) wred[wid][h] = mx[h];
    __syncthreads();
    if (tid < HH) {
        float v = wred[0][tid];
        for (int w = 1; w < 8; w++) v = fmaxf(v, wred[w][tid]);
        smax[tid] = v;
    }
    __syncthreads();

    // phase 2: per-head sum of exp
    float sm[HH];
#pragma unroll
    for (int h = 0; h < HH; h++) sm[h] = 0.f;
    for (int t = st + tid; t < en; t += 256) {
#pragma unroll
        for (int h = 0; h < HH; h++) sm[h] += __expf(abase[(size_t)h * TT_ + t] - smax[h]);
    }
#pragma unroll
    for (int h = 0; h < HH; h++) sm[h] = warp_red_sum(sm[h]);
    if (lane == 0)
        for (int h = 0; h < HH; h++) wred[wid][h] = sm[h];
    __syncthreads();
    if (tid < HH) {
        float v = 0.f;
        for (int w = 0; w < 8; w++) v += wred[w][tid];
        sinv[tid] = 1.f / v;
    }
    __syncthreads();

    // phase 3: thread owns channels c0=tid, c1=tid+256
    float acc0[HH], acc1[HH];
#pragma unroll
    for (int h = 0; h < HH; h++) { acc0[h] = 0.f; acc1[h] = 0.f; }

    int t_lo = st & ~15;
    for (int mega = t_lo; mega < en; mega += MEGA) {
        // stage probabilities for this mega-chunk: ps[j*8+h]
#pragma unroll
        for (int k = 0; k < 8; k++) {
            int idx = tid + k * 256;
            int j = idx >> 3, h = idx & 7;
            int t = mega + j;
            float v = 0.f;
            if (t >= st && t < en)
                v = __expf(abase[(size_t)h * TT_ + t] - smax[h]) * sinv[h];
            ps[idx] = v;
        }
        __syncthreads();

        int mend = min(mega + MEGA, en);
        int nch = (mend - mega + 15) >> 4;

        seg_prefetch(tile0, ebase, mega, tid);
        asm volatile("cp.async.commit_group;\n" ::: "memory");

        for (int ci = 0; ci < nch; ci++) {
            float* tb = (ci & 1) ? tile1 : tile0;
            float* tn = (ci & 1) ? tile0 : tile1;
            bool more = (ci + 1 < nch);
            if (more) {
                seg_prefetch(tn, ebase, mega + (ci + 1) * 16, tid);
                asm volatile("cp.async.commit_group;\n" ::: "memory");
                asm volatile("cp.async.wait_group 1;\n" ::: "memory");
            } else {
                asm volatile("cp.async.wait_group 0;\n" ::: "memory");
            }
            __syncthreads();

            const float* pj = ps + ci * 16 * 8;
            const float* r0 = tb + tid * TSTR;
            const float* r1 = tb + (tid + 256) * TSTR;
#pragma unroll
            for (int jg = 0; jg < 4; jg++) {
                float4 e0 = *(const float4*)(r0 + jg * 4);
                float4 e1 = *(const float4*)(r1 + jg * 4);
                float ea[4] = {e0.x, e0.y, e0.z, e0.w};
                float eb[4] = {e1.x, e1.y, e1.z, e1.w};
#pragma unroll
                for (int jj = 0; jj < 4; jj++) {
                    float4 pA = *(const float4*)(pj + (jg * 4 + jj) * 8);
                    float4 pB = *(const float4*)(pj + (jg * 4 + jj) * 8 + 4);
                    float p[8] = {pA.x, pA.y, pA.z, pA.w, pB.x, pB.y, pB.z, pB.w};
#pragma unroll
                    for (int h = 0; h < HH; h++) {
                        acc0[h] = fmaf(p[h], ea[jj], acc0[h]);
                        acc1[h] = fmaf(p[h], eb[jj], acc1[h]);
                    }
                }
            }
            __syncthreads();  // compute done before this buffer is refilled
        }
    }

    float* mo = g_m + (size_t)bid * HH * CC;
#pragma unroll
    for (int h = 0; h < HH; h++) {
        mo[h * CC + tid] = acc0[h];
        mo[h * CC + tid + 256] = acc1[h];
    }
}

// ---------------------------------------------------------------------------
// fp32 tiled GEMM, 64x64 tile, split-K via [kbeg,kend), atomicAdd epilogue.
// C[m,n] += sum_k A[m,k]*B[n,k]. 256 threads, 4x4 micro.
// ---------------------------------------------------------------------------
__device__ __forceinline__ void gemm_body(const float* __restrict__ A,
                                          const float* __restrict__ Bm,
                                          float* __restrict__ Cm,
                                          int lda, int ldb, int ldc, int kbeg, int kend) {
    __shared__ float As[32][68];
    __shared__ float Bs[32][68];
    int tid = threadIdx.x;
    int tx = tid & 15, ty = tid >> 4;
    int m0 = blockIdx.x * 64, n0 = blockIdx.y * 64;
    float acc[4][4];
#pragma unroll
    for (int i = 0; i < 4; i++)
#pragma unroll
        for (int j = 0; j < 4; j++) acc[i][j] = 0.f;

    for (int k0 = kbeg; k0 < kend; k0 += 32) {
#pragma unroll
        for (int i = 0; i < 8; i++) {
            int idx = tid + i * 256;
            int row = idx >> 5, col = idx & 31;
            As[col][row] = A[(size_t)(m0 + row) * lda + k0 + col];
            Bs[col][row] = Bm[(size_t)(n0 + row) * ldb + k0 + col];
        }
        __syncthreads();
#pragma unroll
        for (int kk = 0; kk < 32; kk++) {
            float4 a4 = *(const float4*)&As[kk][ty * 4];
            float4 b4 = *(const float4*)&Bs[kk][tx * 4];
            float a[4] = {a4.x, a4.y, a4.z, a4.w};
            float bb[4] = {b4.x, b4.y, b4.z, b4.w};
#pragma unroll
            for (int i = 0; i < 4; i++)
#pragma unroll
                for (int j = 0; j < 4; j++) acc[i][j] = fmaf(a[i], bb[j], acc[i][j]);
        }
        __syncthreads();
    }
#pragma unroll
    for (int i = 0; i < 4; i++) {
        int mm = m0 + ty * 4 + i;
#pragma unroll
        for (int j = 0; j < 4; j++) {
            int nn = n0 + tx * 4 + j;
            atomicAdd(&Cm[(size_t)mm * ldc + nn], acc[i][j]);
        }
    }
}

// D1: tmp[r, h*64+d] += sum_c m[r,h,c]*Wv[h*64+d,c].  grid (16, 1, 16): z = h*2 + ksplit
__global__ void gemm1_kernel(const float* __restrict__ Wv) {
    int h = blockIdx.z >> 1;
    int kb = (blockIdx.z & 1) * 256;
    gemm_body(g_m + h * CC, Wv + (size_t)h * DD * CC, g_tmp + h * DD,
              HH * CC, CC, CC, kb, kb + 256);
}

// D2: out[r,o] += sum_i tmp[r,i]*Wp[o,i].  grid (16, 8, 2)
__global__ void gemm2_kernel(const float* __restrict__ Wp, float* __restrict__ out) {
    int kb = blockIdx.z * 256;
    gemm_body(g_tmp, Wp, out, CC, CC, CC, kb, kb + 256);
}

// ---------------------------------------------------------------------------
extern "C" void kernel_launch(void* const* d_in, const int* in_sizes, int n_in,
                              void* d_out, int out_size) {
    const float* x  = (const float*)d_in[0];
    const float* eh = (const float*)d_in[1];
    const int*   st = (const int*)d_in[2];
    const int*   en = (const int*)d_in[3];
    const float* Wq = (const float*)d_in[4];
    const float* bq = (const float*)d_in[5];
    const float* Wk = (const float*)d_in[6];
    /* d_in[7] = bk: constant per head in logits, cancels in softmax */
    const float* Wv = (const float*)d_in[8];
    const float* bv = (const float*)d_in[9];
    const float* Wp = (const float*)d_in[10];
    const float* bp = (const float*)d_in[11];
    float* out = (float*)d_out;

    cudaFuncSetAttribute(seg_kernel, cudaFuncAttributeMaxDynamicSharedMemorySize,
                         SEG_SMEM);

    setup1_kernel<<<32, 512>>>(x, Wq, bq, Wp, bv, bp);
    setup2_kernel<<<HH, CC>>>(Wk);
    init_kernel<<<2048, 256>>>(out);
    att_kernel<<<dim3(TT_ / 256, BB, CSPLIT), 256>>>(eh);
    seg_kernel<<<BB * SS, 256, SEG_SMEM>>>(eh, st, en);
    gemm1_kernel<<<dim3(16, 1, 16), 256>>>(Wv);
    gemm2_kernel<<<dim3(16, 8, 2), 256>>>(Wp, out);
}